// round 13
// baseline (speedup 1.0000x reference)
#include <cuda_runtime.h>
#include <cuda_bf16.h>
#include <stdint.h>
#include <math.h>

#define T_ 512
#define B_ 64
#define I_ 1024
#define H_ 1024
#define O_ 1024
#define TB_ (T_ * B_)
#define NBLK 128

// ================== scratch (device globals; no allocations) ==================
__device__ float g_x[3][TB_ * H_];         // xr, xu, xh projections
__device__ float g_h [B_ * H_];            // hidden state fp32
__device__ float g_U [B_ * H_];            // update gate fp32
__device__ unsigned int g_bar_cnt;         // full barrier (end of step)
__device__ unsigned int g_bar_R;           // R-half arrivals after phase A
__device__ unsigned int g_bar_U;           // U-half arrivals after phase A

// int8 dual-plane mirrors, SWIZZLED: addr(r,k) = r*1024 + (((k>>4)^(r&7))<<4) + (k&15)
__device__ int8_t g_h1 [B_ * H_];
__device__ int8_t g_h0 [B_ * H_];
__device__ int8_t g_hR1[B_ * H_];
__device__ int8_t g_hR0[B_ * H_];
__device__ int8_t g_w1RU[2 * H_ * H_];     // [W_hr|W_hu] [n][k] swizzled
__device__ int8_t g_w0RU[2 * H_ * H_];
__device__ int8_t g_w1C[H_ * H_];          // W_hh [n][k] swizzled
__device__ int8_t g_w0C[H_ * H_];

// bf16 split operands for projections (A reused for X and states)
__device__ __nv_bfloat16 g_Ah[TB_ * H_];
__device__ __nv_bfloat16 g_Al[TB_ * H_];
__device__ __nv_bfloat16 g_Bh[4][H_ * H_];
__device__ __nv_bfloat16 g_Bl[4][H_ * H_];

// ================== fused prep: conversions + quant + init =====================
__global__ __launch_bounds__(256) void prep_all(
    const float* __restrict__ X,
    const float* __restrict__ Wxr, const float* __restrict__ Wxu,
    const float* __restrict__ Wxh, const float* __restrict__ Whq,
    const float* __restrict__ Whr, const float* __restrict__ Whu,
    const float* __restrict__ Whh)
{
    const int b = blockIdx.x;
    const int tid = threadIdx.x;
    if (b < 32768) {
        size_t i4 = ((size_t)b * 256 + tid) * 4;
        float4 v = *reinterpret_cast<const float4*>(X + i4);
        float vv[4] = {v.x, v.y, v.z, v.w};
        __align__(8) __nv_bfloat16 hb[4], lb[4];
#pragma unroll
        for (int j = 0; j < 4; j++) {
            __nv_bfloat16 h = __float2bfloat16(vv[j]);
            hb[j] = h;
            lb[j] = __float2bfloat16(vv[j] - __bfloat162float(h));
        }
        *reinterpret_cast<uint2*>(g_Ah + i4) = *reinterpret_cast<const uint2*>(hb);
        *reinterpret_cast<uint2*>(g_Al + i4) = *reinterpret_cast<const uint2*>(lb);
    } else if (b < 49152) {
        int bb = b - 32768;
        int which = bb >> 12;
        int idx = (bb & 4095) * 256 + tid;
        const float* W = which == 0 ? Wxr : which == 1 ? Wxu : which == 2 ? Wxh : Whq;
        int k = idx >> 10, n = idx & (H_ - 1);
        float v = W[idx];
        __nv_bfloat16 h = __float2bfloat16(v);
        __nv_bfloat16 l = __float2bfloat16(v - __bfloat162float(h));
        g_Bh[which][(size_t)n * H_ + k] = h;
        g_Bl[which][(size_t)n * H_ + k] = l;
    } else if (b < 61440) {
        int bb = b - 49152;
        int which = bb >> 12;
        int idx = (bb & 4095) * 256 + tid;
        const float* W = which == 0 ? Whr : which == 1 ? Whu : Whh;
        int8_t* p1 = which == 0 ? g_w1RU : which == 1 ? g_w1RU + (size_t)H_ * H_ : g_w1C;
        int8_t* p0 = which == 0 ? g_w0RU : which == 1 ? g_w0RU + (size_t)H_ * H_ : g_w0C;
        int k = idx >> 10, n = idx & (H_ - 1);
        float v = W[idx];
        int q = __float2int_rn(v * 262144.0f);
        q = max(-32640, min(32639, q));
        int w1 = (q + 128) >> 8;
        int w0 = q - (w1 << 8);
        size_t addr = (size_t)n * 1024 + ((((k >> 4) ^ (n & 7)) << 4) | (k & 15));
        p1[addr] = (int8_t)w1;
        p0[addr] = (int8_t)w0;
    } else {
        int i = (b - 61440) * 256 + tid;
        if (i == 0) { g_bar_cnt = 0; g_bar_R = 0; g_bar_U = 0; }
        if (i < B_ * H_) {
            g_h[i] = 0.0f;
            g_h1[i] = 0;
            g_h0[i] = 0;
        }
    }
}

// ================== PTX helpers ================================================
__device__ __forceinline__ uint32_t s2u(const void* p) {
    uint32_t a;
    asm("{ .reg .u64 t; cvta.to.shared.u64 t, %1; cvt.u32.u64 %0, t; }"
        : "=r"(a) : "l"(p));
    return a;
}
__device__ __forceinline__ void cpa16(uint32_t saddr, const void* g) {
    asm volatile("cp.async.cg.shared.global [%0], [%1], 16;"
                 :: "r"(saddr), "l"(g));
}
__device__ __forceinline__ void bulk_g2s(uint32_t saddr, const void* g,
                                         uint32_t bytes, uint32_t mbar) {
    asm volatile(
        "cp.async.bulk.shared::cluster.global.mbarrier::complete_tx::bytes "
        "[%0], [%1], %2, [%3];"
        :: "r"(saddr), "l"(g), "r"(bytes), "r"(mbar) : "memory");
}
__device__ __forceinline__ void ldsm4(uint32_t* r, uint32_t addr) {
    asm volatile("ldmatrix.sync.aligned.m8n8.x4.shared.b16 {%0,%1,%2,%3}, [%4];"
                 : "=r"(r[0]), "=r"(r[1]), "=r"(r[2]), "=r"(r[3]) : "r"(addr));
}
__device__ __forceinline__ void ldsm2(uint32_t* r, uint32_t addr) {
    asm volatile("ldmatrix.sync.aligned.m8n8.x2.shared.b16 {%0,%1}, [%2];"
                 : "=r"(r[0]), "=r"(r[1]) : "r"(addr));
}
__device__ __forceinline__ void mma16816(float* d, const uint32_t* a,
                                         uint32_t b0, uint32_t b1) {
    asm volatile(
        "mma.sync.aligned.m16n8k16.row.col.f32.bf16.bf16.f32 "
        "{%0,%1,%2,%3}, {%4,%5,%6,%7}, {%8,%9}, {%0,%1,%2,%3};"
        : "+f"(d[0]), "+f"(d[1]), "+f"(d[2]), "+f"(d[3])
        : "r"(a[0]), "r"(a[1]), "r"(a[2]), "r"(a[3]), "r"(b0), "r"(b1));
}
__device__ __forceinline__ void imma32(int* d, const uint32_t* a,
                                       uint32_t b0, uint32_t b1) {
    asm volatile(
        "mma.sync.aligned.m16n8k32.row.col.s32.s8.s8.s32 "
        "{%0,%1,%2,%3}, {%4,%5,%6,%7}, {%8,%9}, {%0,%1,%2,%3};"
        : "+r"(d[0]), "+r"(d[1]), "+r"(d[2]), "+r"(d[3])
        : "r"(a[0]), "r"(a[1]), "r"(a[2]), "r"(a[3]), "r"(b0), "r"(b1));
}
#define MBAR_WAIT(mbar, ph) do {                                              \
    asm volatile(                                                             \
        "{\n\t.reg .pred P1;\n\t"                                             \
        "W_%=:\n\t"                                                           \
        "mbarrier.try_wait.parity.acquire.cta.shared::cta.b64 P1, [%0], %1, 0x989680;\n\t" \
        "@P1 bra D_%=;\n\t"                                                   \
        "bra.uni W_%=;\n\t"                                                   \
        "D_%=:\n\t}"                                                          \
        :: "r"(mbar), "r"((unsigned)(ph)) : "memory");                        \
} while (0)

// ================== HMMA GEMM (projections): KC=32, 2 CTAs/SM =================
#define KC 32
#define GSTR2 40
#define SMAT2 (128 * GSTR2)
#define GEMM_SMEM (2 * 4 * SMAT2 * 2)

struct ProjOut { const float* b[3]; float* c[3]; };

__global__ __launch_bounds__(256, 2)
void hmma_gemm3_kernel(const __nv_bfloat16* __restrict__ Ah,
                       const __nv_bfloat16* __restrict__ Al,
                       const __nv_bfloat16* __restrict__ Bh,
                       const __nv_bfloat16* __restrict__ Bl,
                       ProjOut po)
{
    extern __shared__ __nv_bfloat16 smx[];
    const uint32_t sbase = s2u(smx);

    const int tid  = threadIdx.x;
    const int nt   = blockIdx.x;
    const int mt   = blockIdx.y;
    const int wid  = tid >> 5;
    const int lane = tid & 31;
    const int wm   = wid & 3;
    const int wn   = wid >> 2;

    const int m0 = mt * 128;
    const int n0 = nt * 128;

    const uint32_t loff = (uint32_t)((lane & 15) * GSTR2 + ((lane >> 4) << 3));

    float acc[2][8][4];
#pragma unroll
    for (int i = 0; i < 2; i++)
#pragma unroll
        for (int j = 0; j < 8; j++)
#pragma unroll
            for (int q = 0; q < 4; q++) acc[i][j][q] = 0.0f;

    auto load_chunk = [&](int kc, int buf) {
        const __nv_bfloat16* gsrc[4] = {
            Ah + (size_t)m0 * H_ + kc * KC,
            Al + (size_t)m0 * H_ + kc * KC,
            Bh + (size_t)n0 * H_ + kc * KC,
            Bl + (size_t)n0 * H_ + kc * KC };
#pragma unroll
        for (int mat = 0; mat < 4; mat++) {
            const __nv_bfloat16* g = gsrc[mat];
            const uint32_t mb = sbase + 2u * ((buf * 4 + mat) * SMAT2);
#pragma unroll
            for (int p = 0; p < 2; p++) {
                int idx = tid + p * 256;
                int row = idx >> 2, unit = idx & 3;
                cpa16(mb + 2u * (row * GSTR2 + unit * 8),
                      g + (size_t)row * H_ + unit * 8);
            }
        }
    };

    load_chunk(0, 0);
    asm volatile("cp.async.commit_group;");

    for (int kc = 0; kc < 32; kc++) {
        const int buf = kc & 1;
        if (kc < 31) {
            load_chunk(kc + 1, buf ^ 1);
            asm volatile("cp.async.commit_group;");
            asm volatile("cp.async.wait_group 1;");
        } else {
            asm volatile("cp.async.wait_group 0;");
        }
        __syncthreads();

        const uint32_t bAh = sbase + 2u * ((buf * 4 + 0) * SMAT2);
        const uint32_t bAl = sbase + 2u * ((buf * 4 + 1) * SMAT2);
        const uint32_t bBh = sbase + 2u * ((buf * 4 + 2) * SMAT2);
        const uint32_t bBl = sbase + 2u * ((buf * 4 + 3) * SMAT2);

#pragma unroll
        for (int ks = 0; ks < 2; ks++) {
            const uint32_t coff = 2u * (ks * 16) + 2u * loff;
            uint32_t aH[2][4], aL[2][4], bH[4][4], bL[4][4];
#pragma unroll
            for (int im = 0; im < 2; im++) {
                uint32_t ro = 2u * ((wm * 32 + im * 16) * GSTR2);
                ldsm4(aH[im], bAh + ro + coff);
                ldsm4(aL[im], bAl + ro + coff);
            }
#pragma unroll
            for (int ib = 0; ib < 4; ib++) {
                uint32_t ro = 2u * ((wn * 64 + ib * 16) * GSTR2);
                ldsm4(bH[ib], bBh + ro + coff);
                ldsm4(bL[ib], bBl + ro + coff);
            }
#pragma unroll
            for (int im = 0; im < 2; im++)
#pragma unroll
                for (int ib = 0; ib < 4; ib++)
#pragma unroll
                    for (int hf = 0; hf < 2; hf++) {
                        float* d = acc[im][ib * 2 + hf];
                        mma16816(d, aH[im], bH[ib][hf], bH[ib][hf + 2]);
                        mma16816(d, aH[im], bL[ib][hf], bL[ib][hf + 2]);
                        mma16816(d, aL[im], bH[ib][hf], bH[ib][hf + 2]);
                    }
        }
        __syncthreads();
    }

    const int sel  = nt >> 3;
    const int ncol = (nt & 7) * 128;
    float* C = po.c[sel];
    const float* bias = po.b[sel];

#pragma unroll
    for (int im = 0; im < 2; im++) {
        const int mg = m0 + wm * 32 + im * 16 + (lane >> 2);
#pragma unroll
        for (int nb = 0; nb < 8; nb++) {
            const int ng = ncol + wn * 64 + nb * 8 + (lane & 3) * 2;
            const float bx = bias[ng], by = bias[ng + 1];
            float2 o0, o1;
            o0.x = acc[im][nb][0] + bx; o0.y = acc[im][nb][1] + by;
            o1.x = acc[im][nb][2] + bx; o1.y = acc[im][nb][3] + by;
            *reinterpret_cast<float2*>(C + (size_t)mg * 1024 + ng)       = o0;
            *reinterpret_cast<float2*>(C + (size_t)(mg + 8) * 1024 + ng) = o1;
        }
    }
}

// ================== global barrier primitives (no L1 flush) ====================
__device__ __forceinline__ void bar_arrive(unsigned int* ctr) {
    __syncthreads();
    if (threadIdx.x == 0)
        asm volatile("red.release.gpu.global.add.u32 [%0], 1;"
                     :: "l"(ctr) : "memory");
}
__device__ __forceinline__ void bar_wait(unsigned int* ctr, unsigned int target) {
    if (threadIdx.x == 0) {
        unsigned int v;
        do {
            asm volatile("ld.acquire.gpu.global.u32 %0, [%1];"
                         : "=r"(v) : "l"(ctr) : "memory");
        } while (v < target);
    }
    __syncthreads();
}

// ================== int8 persistent GRU (split A->B barrier) ===================
#define SW1A 0
#define SW0A 16384
#define SW1B 32768
#define SW0B 40960
#define SH1  49152
#define SH0  114688
#define MBOF 180224
#define REDOF 180288
#define RSMEM (180288 + 6144)
#define S_HI (1.0f / 65536.0f)
#define S_MID (1.0f / 16777216.0f)

__global__ __launch_bounds__(256, 1) void gru_int8_kernel(float* __restrict__ states)
{
    extern __shared__ int8_t sm8[];
    const uint32_t sbase = s2u(sm8);
    const uint32_t mb0 = sbase + MBOF;

    const int tid  = threadIdx.x;
    const int bid  = blockIdx.x;
    const int wid  = tid >> 5;
    const int lane = tid & 31;

    const int a_n0 = bid * 16;
    const int a_wm = wid & 3, a_wn = wid >> 2;
    const int b_n0 = bid * 8;

    const uint32_t rA_a = (uint32_t)(a_wm * 16 + (lane & 15));
    const uint32_t selA = (uint32_t)(lane >> 4);
    const uint32_t rB_a = (uint32_t)(a_wn * 8 + (lane & 7));
    const uint32_t selB = (uint32_t)((lane >> 3) & 1);
    const uint32_t rA_b = (uint32_t)((wid & 3) * 16 + (lane & 15));
    const uint32_t rB_b = (uint32_t)(lane & 7);

    // ---- one-time: mbarriers + resident W tiles ----
    if (tid == 0) {
#pragma unroll
        for (int c = 0; c < 4; c++)
            asm volatile("mbarrier.init.shared.b64 [%0], 1;"
                         :: "r"(mb0 + c * 8) : "memory");
    }
    {
        const int8_t* W1A = g_w1RU + (size_t)a_n0 * 1024;
        const int8_t* W0A = g_w0RU + (size_t)a_n0 * 1024;
        const int8_t* W1B = g_w1C + (size_t)b_n0 * 1024;
        const int8_t* W0B = g_w0C + (size_t)b_n0 * 1024;
        for (int i = tid; i < 1024; i += 256) {
            uint32_t bo = (uint32_t)i * 16;
            cpa16(sbase + SW1A + bo, W1A + (size_t)i * 16);
            cpa16(sbase + SW0A + bo, W0A + (size_t)i * 16);
        }
        for (int i = tid; i < 512; i += 256) {
            uint32_t bo = (uint32_t)i * 16;
            cpa16(sbase + SW1B + bo, W1B + (size_t)i * 16);
            cpa16(sbase + SW0B + bo, W0B + (size_t)i * 16);
        }
        asm volatile("cp.async.commit_group;");
        asm volatile("cp.async.wait_group 0;");
    }
    __syncthreads();

    int par = 0;

    for (int t = 0; t < T_; t++) {
        const size_t xbase = (size_t)t * B_ * H_;
        const unsigned int half_t = (unsigned)(t + 1) * 64;

        // ======================= phase A: gates ===============================
        {
            const int gc = a_n0 + a_wn * 8 + (lane & 3) * 2;
            const int xc = gc & (H_ - 1);
            const float* xp = (bid < 64) ? g_x[0] : g_x[1];
            float2 xv[2], hv[2];
#pragma unroll
            for (int i = 0; i < 2; i++) {
                const int row = a_wm * 16 + (lane >> 2) + i * 8;
                const size_t off = (size_t)row * H_ + xc;
                xv[i] = __ldcg(reinterpret_cast<const float2*>(xp + xbase + off));
                if (bid < 64)
                    hv[i] = __ldcg(reinterpret_cast<const float2*>(g_h + off));
            }
            // stage h planes (parallel issue, 4 lanes)
            if (tid < 4) {
                const int c = tid;
                asm volatile("mbarrier.arrive.expect_tx.shared.b64 _, [%0], %1;"
                             :: "r"(mb0 + c * 8), "r"(32768u) : "memory");
                bulk_g2s(sbase + SH1 + c * 16384, g_h1 + c * 16384, 16384u, mb0 + c * 8);
                bulk_g2s(sbase + SH0 + c * 16384, g_h0 + c * 16384, 16384u, mb0 + c * 8);
            }
            MBAR_WAIT(mb0 + a_wm * 8, par);

            int dhi[4] = {0,0,0,0}, dmA[4] = {0,0,0,0}, dmB[4] = {0,0,0,0};
            const uint32_t baseA1 = sbase + SH1 + rA_a * 1024;
            const uint32_t baseA0 = sbase + SH0 + rA_a * 1024;
            const uint32_t baseB1 = sbase + SW1A + rB_a * 1024;
            const uint32_t baseB0 = sbase + SW0A + rB_a * 1024;
            const uint32_t swA = rA_a & 7, swB = rB_a & 7;
#pragma unroll 8
            for (int ks = 0; ks < 32; ks++) {
                const uint32_t uA = (((uint32_t)ks * 2 + selA) ^ swA) << 4;
                const uint32_t uB = (((uint32_t)ks * 2 + selB) ^ swB) << 4;
                uint32_t a1[4], a0[4], b1[2], b0[2];
                ldsm4(a1, baseA1 + uA);
                ldsm4(a0, baseA0 + uA);
                ldsm2(b1, baseB1 + uB);
                ldsm2(b0, baseB0 + uB);
                imma32(dhi, a1, b1[0], b1[1]);
                imma32(dmA, a1, b0[0], b0[1]);
                imma32(dmB, a0, b1[0], b1[1]);
            }

            // epilogue A
#pragma unroll
            for (int i = 0; i < 2; i++) {
                const int row = a_wm * 16 + (lane >> 2) + i * 8;
                const size_t off = (size_t)row * H_ + xc;
                float z0 = (float)dhi[2*i+0] * S_HI
                         + (float)(dmA[2*i+0] + dmB[2*i+0]) * S_MID + xv[i].x;
                float z1 = (float)dhi[2*i+1] * S_HI
                         + (float)(dmA[2*i+1] + dmB[2*i+1]) * S_MID + xv[i].y;
                float s0 = 1.0f / (1.0f + __expf(-z0));
                float s1 = 1.0f / (1.0f + __expf(-z1));
                if (bid < 64) {
                    float v0 = hv[i].x * s0, v1 = hv[i].y * s1;
                    int q0 = __float2int_rn(v0 * 16384.0f);
                    int q1 = __float2int_rn(v1 * 16384.0f);
                    int p0 = (q0 + 128) >> 8, p1 = (q1 + 128) >> 8;
                    int r0 = q0 - (p0 << 8), r1 = q1 - (p1 << 8);
                    unsigned short hi2 = (unsigned short)((p0 & 0xFF) | ((p1 & 0xFF) << 8));
                    unsigned short lo2 = (unsigned short)((r0 & 0xFF) | ((r1 & 0xFF) << 8));
                    size_t sa = (size_t)row * 1024 +
                                ((((xc >> 4) ^ (row & 7)) << 4) | (xc & 15));
                    __stcg(reinterpret_cast<unsigned short*>(g_hR1 + sa), hi2);
                    __stcg(reinterpret_cast<unsigned short*>(g_hR0 + sa), lo2);
                } else {
                    __stcg(reinterpret_cast<float2*>(g_U + off), make_float2(s0, s1));
                }
            }
        }
        par ^= 1;
        // split half-barriers: R producers vs U producers
        bar_arrive(bid < 64 ? &g_bar_R : &g_bar_U);

        // ================= phase B: candidate + update ========================
        {
            const int gc = b_n0 + (lane & 3) * 2;
            float2 xv[2], hv[2];
            if (wid < 4) {
#pragma unroll
                for (int i = 0; i < 2; i++) {
                    const int row = wid * 16 + (lane >> 2) + i * 8;
                    const size_t off = (size_t)row * H_ + gc;
                    xv[i] = __ldcg(reinterpret_cast<const float2*>(g_x[2] + xbase + off));
                    hv[i] = __ldcg(reinterpret_cast<const float2*>(g_h + off));
                }
            }
            // wait only for hR producers before staging
            bar_wait(&g_bar_R, half_t);

            if (tid < 4) {
                const int c = tid;
                asm volatile("mbarrier.arrive.expect_tx.shared.b64 _, [%0], %1;"
                             :: "r"(mb0 + c * 8), "r"(32768u) : "memory");
                bulk_g2s(sbase + SH1 + c * 16384, g_hR1 + c * 16384, 16384u, mb0 + c * 8);
                bulk_g2s(sbase + SH0 + c * 16384, g_hR0 + c * 16384, 16384u, mb0 + c * 8);
            }
            MBAR_WAIT(mb0 + (wid & 3) * 8, par);

            int dhi[4] = {0,0,0,0}, dmA[4] = {0,0,0,0}, dmB[4] = {0,0,0,0};
            {
                const uint32_t baseA1 = sbase + SH1 + rA_b * 1024;
                const uint32_t baseA0 = sbase + SH0 + rA_b * 1024;
                const uint32_t baseB1 = sbase + SW1B + rB_b * 1024;
                const uint32_t baseB0 = sbase + SW0B + rB_b * 1024;
                const uint32_t swA = rA_b & 7, swB = rB_b & 7;
                const int ks0 = (wid >> 2) * 16;
#pragma unroll 8
                for (int ks = ks0; ks < ks0 + 16; ks++) {
                    const uint32_t uA = (((uint32_t)ks * 2 + selA) ^ swA) << 4;
                    const uint32_t uB = (((uint32_t)ks * 2 + selB) ^ swB) << 4;
                    uint32_t a1[4], a0[4], b1[2], b0[2];
                    ldsm4(a1, baseA1 + uA);
                    ldsm4(a0, baseA0 + uA);
                    ldsm2(b1, baseB1 + uB);
                    ldsm2(b0, baseB0 + uB);
                    imma32(dhi, a1, b1[0], b1[1]);
                    imma32(dmA, a1, b0[0], b0[1]);
                    imma32(dmB, a0, b1[0], b1[1]);
                }
            }
            // deferred wait for U producers (overlapped with staging + MMA above)
            bar_wait(&g_bar_U, half_t);

            if (wid >= 4) {
                int* rb = reinterpret_cast<int*>(sm8 + REDOF)
                          + (((wid - 4) * 32 + lane) * 12);
#pragma unroll
                for (int j = 0; j < 4; j++) { rb[j] = dhi[j]; rb[4 + j] = dmA[j]; rb[8 + j] = dmB[j]; }
            }
            __syncthreads();
            if (wid < 4) {
                const int* rb = reinterpret_cast<const int*>(sm8 + REDOF)
                                + ((wid * 32 + lane) * 12);
#pragma unroll
                for (int j = 0; j < 4; j++) { dhi[j] += rb[j]; dmA[j] += rb[4 + j]; dmB[j] += rb[8 + j]; }

#pragma unroll
                for (int i = 0; i < 2; i++) {
                    const int row = wid * 16 + (lane >> 2) + i * 8;
                    const size_t off = (size_t)row * H_ + gc;
                    float2 uv = __ldcg(reinterpret_cast<const float2*>(g_U + off));
                    float z0 = (float)dhi[2*i+0] * S_HI
                             + (float)(dmA[2*i+0] + dmB[2*i+0]) * S_MID + xv[i].x;
                    float z1 = (float)dhi[2*i+1] * S_HI
                             + (float)(dmA[2*i+1] + dmB[2*i+1]) * S_MID + xv[i].y;
                    float hc0 = tanhf(z0), hc1 = tanhf(z1);
                    float hn0 = uv.x * hv[i].x + (1.0f - uv.x) * hc0;
                    float hn1 = uv.y * hv[i].y + (1.0f - uv.y) * hc1;
                    __stcg(reinterpret_cast<float2*>(g_h + off), make_float2(hn0, hn1));
                    __stcg(reinterpret_cast<float2*>(states + xbase + off),
                           make_float2(hn0, hn1));
                    __nv_bfloat16 b0 = __float2bfloat16(hn0);
                    __nv_bfloat16 b1 = __float2bfloat16(hn1);
                    unsigned short u0 = *reinterpret_cast<unsigned short*>(&b0);
                    unsigned short u1 = *reinterpret_cast<unsigned short*>(&b1);
                    __nv_bfloat16 l0 = __float2bfloat16(hn0 - __bfloat162float(b0));
                    __nv_bfloat16 l1 = __float2bfloat16(hn1 - __bfloat162float(b1));
                    unsigned short v0 = *reinterpret_cast<unsigned short*>(&l0);
                    unsigned short v1 = *reinterpret_cast<unsigned short*>(&l1);
                    __stcg(reinterpret_cast<unsigned int*>(g_Ah + xbase + off),
                           ((unsigned)u1 << 16) | u0);
                    __stcg(reinterpret_cast<unsigned int*>(g_Al + xbase + off),
                           ((unsigned)v1 << 16) | v0);
                    int q0 = __float2int_rn(hn0 * 16384.0f);
                    int q1 = __float2int_rn(hn1 * 16384.0f);
                    int p0 = (q0 + 128) >> 8, p1 = (q1 + 128) >> 8;
                    int r0 = q0 - (p0 << 8), r1 = q1 - (p1 << 8);
                    unsigned short hi2 = (unsigned short)((p0 & 0xFF) | ((p1 & 0xFF) << 8));
                    unsigned short lo2 = (unsigned short)((r0 & 0xFF) | ((r1 & 0xFF) << 8));
                    size_t sa = (size_t)row * 1024 +
                                ((((gc >> 4) ^ (row & 7)) << 4) | (gc & 15));
                    __stcg(reinterpret_cast<unsigned short*>(g_h1 + sa), hi2);
                    __stcg(reinterpret_cast<unsigned short*>(g_h0 + sa), lo2);
                }
            }
        }
        par ^= 1;
        // full barrier: h(t+1) complete before phase A of t+1
        bar_arrive(&g_bar_cnt);
        bar_wait(&g_bar_cnt, (unsigned)(t + 1) * NBLK);
    }
}

// ================== launcher ===================================================
extern "C" void kernel_launch(void* const* d_in, const int* in_sizes, int n_in,
                              void* d_out, int out_size)
{
    const float* X    = (const float*)d_in[0];
    const float* W_xr = (const float*)d_in[1];
    const float* W_xu = (const float*)d_in[2];
    const float* W_xh = (const float*)d_in[3];
    const float* W_hr = (const float*)d_in[4];
    const float* W_hu = (const float*)d_in[5];
    const float* W_hh = (const float*)d_in[6];
    const float* b_r  = (const float*)d_in[7];
    const float* b_u  = (const float*)d_in[8];
    const float* b_h  = (const float*)d_in[9];
    const float* W_hq = (const float*)d_in[10];
    const float* b_q  = (const float*)d_in[11];

    float* out     = (float*)d_out;
    float* outputs = out;                        // [T,B,O]
    float* states  = out + (size_t)TB_ * O_;     // [T,B,H]

    void *p_x, *p_ah, *p_al, *p_bh, *p_bl;
    cudaGetSymbolAddress(&p_x, g_x);
    cudaGetSymbolAddress(&p_ah, g_Ah);
    cudaGetSymbolAddress(&p_al, g_Al);
    cudaGetSymbolAddress(&p_bh, g_Bh);
    cudaGetSymbolAddress(&p_bl, g_Bl);

    float* xbuf = (float*)p_x;
    __nv_bfloat16* Ah = (__nv_bfloat16*)p_ah;
    __nv_bfloat16* Al = (__nv_bfloat16*)p_al;
    __nv_bfloat16* Bh = (__nv_bfloat16*)p_bh;
    __nv_bfloat16* Bl = (__nv_bfloat16*)p_bl;

    static int smem_set = 0;
    if (!smem_set) {
        cudaFuncSetAttribute(hmma_gemm3_kernel,
                             cudaFuncAttributeMaxDynamicSharedMemorySize, GEMM_SMEM);
        cudaFuncSetAttribute(gru_int8_kernel,
                             cudaFuncAttributeMaxDynamicSharedMemorySize, RSMEM);
        smem_set = 1;
    }

    // 0: fused prep
    prep_all<<<61696, 256>>>(X, W_xr, W_xu, W_xh, W_hq, W_hr, W_hu, W_hh);
    // 1: fused input projections
    {
        ProjOut po;
        po.b[0] = b_r; po.b[1] = b_u; po.b[2] = b_h;
        po.c[0] = xbuf; po.c[1] = xbuf + (size_t)TB_ * H_; po.c[2] = xbuf + 2 * (size_t)TB_ * H_;
        dim3 gg(24, TB_ / 128);
        hmma_gemm3_kernel<<<gg, 256, GEMM_SMEM>>>(Ah, Al, Bh, Bl, po);
    }
    // 2: recurrence
    gru_int8_kernel<<<NBLK, 256, RSMEM>>>(states);
    // 3: output projection
    {
        ProjOut po;
        po.b[0] = b_q; po.b[1] = b_q; po.b[2] = b_q;
        po.c[0] = outputs; po.c[1] = outputs; po.c[2] = outputs;
        dim3 gg(8, TB_ / 128);
        hmma_gemm3_kernel<<<gg, 256, GEMM_SMEM>>>(Ah, Al, Bh + 3 * (size_t)H_ * H_,
                                                  Bl + 3 * (size_t)H_ * H_, po);
    }
}

// round 14
// speedup vs baseline: 1.0898x; 1.0898x over previous
#include <cuda_runtime.h>
#include <cuda_bf16.h>
#include <stdint.h>
#include <math.h>

#define T_ 512
#define B_ 64
#define I_ 1024
#define H_ 1024
#define O_ 1024
#define TB_ (T_ * B_)
#define NBLK 128

// ================== scratch (device globals; no allocations) ==================
__device__ float g_x[3][TB_ * H_];         // xr, xu, xh projections
__device__ float g_h [B_ * H_];            // hidden state fp32
__device__ float g_U [B_ * H_];            // update gate fp32
__device__ unsigned int g_bar_cnt;

// int8 dual-plane mirrors, SWIZZLED: addr(r,k) = r*1024 + (((k>>4)^(r&7))<<4) + (k&15)
__device__ int8_t g_h1 [B_ * H_];
__device__ int8_t g_h0 [B_ * H_];
__device__ int8_t g_hR1[B_ * H_];
__device__ int8_t g_hR0[B_ * H_];
__device__ int8_t g_w1RU[2 * H_ * H_];
__device__ int8_t g_w0RU[2 * H_ * H_];
__device__ int8_t g_w1C[H_ * H_];
__device__ int8_t g_w0C[H_ * H_];

// bf16 split operands
__device__ __nv_bfloat16 g_Ah[TB_ * H_];   // X hi/lo (input projection A)
__device__ __nv_bfloat16 g_Al[TB_ * H_];
__device__ __nv_bfloat16 g_Sh[TB_ * H_];   // states hi/lo (output projection A)
__device__ __nv_bfloat16 g_Sl[TB_ * H_];
__device__ __nv_bfloat16 g_Bh[4][H_ * H_];
__device__ __nv_bfloat16 g_Bl[4][H_ * H_];

// ================== fused prep: conversions + quant + init =====================
__global__ __launch_bounds__(256) void prep_all(
    const float* __restrict__ X,
    const float* __restrict__ Wxr, const float* __restrict__ Wxu,
    const float* __restrict__ Wxh, const float* __restrict__ Whq,
    const float* __restrict__ Whr, const float* __restrict__ Whu,
    const float* __restrict__ Whh)
{
    const int b = blockIdx.x;
    const int tid = threadIdx.x;
    if (b < 32768) {
        size_t i4 = ((size_t)b * 256 + tid) * 4;
        float4 v = *reinterpret_cast<const float4*>(X + i4);
        float vv[4] = {v.x, v.y, v.z, v.w};
        __align__(8) __nv_bfloat16 hb[4], lb[4];
#pragma unroll
        for (int j = 0; j < 4; j++) {
            __nv_bfloat16 h = __float2bfloat16(vv[j]);
            hb[j] = h;
            lb[j] = __float2bfloat16(vv[j] - __bfloat162float(h));
        }
        *reinterpret_cast<uint2*>(g_Ah + i4) = *reinterpret_cast<const uint2*>(hb);
        *reinterpret_cast<uint2*>(g_Al + i4) = *reinterpret_cast<const uint2*>(lb);
    } else if (b < 49152) {
        int bb = b - 32768;
        int which = bb >> 12;
        int idx = (bb & 4095) * 256 + tid;
        const float* W = which == 0 ? Wxr : which == 1 ? Wxu : which == 2 ? Wxh : Whq;
        int k = idx >> 10, n = idx & (H_ - 1);
        float v = W[idx];
        __nv_bfloat16 h = __float2bfloat16(v);
        __nv_bfloat16 l = __float2bfloat16(v - __bfloat162float(h));
        g_Bh[which][(size_t)n * H_ + k] = h;
        g_Bl[which][(size_t)n * H_ + k] = l;
    } else if (b < 61440) {
        int bb = b - 49152;
        int which = bb >> 12;
        int idx = (bb & 4095) * 256 + tid;
        const float* W = which == 0 ? Whr : which == 1 ? Whu : Whh;
        int8_t* p1 = which == 0 ? g_w1RU : which == 1 ? g_w1RU + (size_t)H_ * H_ : g_w1C;
        int8_t* p0 = which == 0 ? g_w0RU : which == 1 ? g_w0RU + (size_t)H_ * H_ : g_w0C;
        int k = idx >> 10, n = idx & (H_ - 1);
        float v = W[idx];
        int q = __float2int_rn(v * 262144.0f);
        q = max(-32640, min(32639, q));
        int w1 = (q + 128) >> 8;
        int w0 = q - (w1 << 8);
        size_t addr = (size_t)n * 1024 + ((((k >> 4) ^ (n & 7)) << 4) | (k & 15));
        p1[addr] = (int8_t)w1;
        p0[addr] = (int8_t)w0;
    } else {
        int i = (b - 61440) * 256 + tid;
        if (i == 0) g_bar_cnt = 0;
        if (i < B_ * H_) {
            g_h[i] = 0.0f;
            g_h1[i] = 0;
            g_h0[i] = 0;
        }
    }
}

// ================== PTX helpers ================================================
__device__ __forceinline__ uint32_t s2u(const void* p) {
    uint32_t a;
    asm("{ .reg .u64 t; cvta.to.shared.u64 t, %1; cvt.u32.u64 %0, t; }"
        : "=r"(a) : "l"(p));
    return a;
}
__device__ __forceinline__ void cpa16(uint32_t saddr, const void* g) {
    asm volatile("cp.async.cg.shared.global [%0], [%1], 16;"
                 :: "r"(saddr), "l"(g));
}
__device__ __forceinline__ void bulk_g2s(uint32_t saddr, const void* g,
                                         uint32_t bytes, uint32_t mbar) {
    asm volatile(
        "cp.async.bulk.shared::cluster.global.mbarrier::complete_tx::bytes "
        "[%0], [%1], %2, [%3];"
        :: "r"(saddr), "l"(g), "r"(bytes), "r"(mbar) : "memory");
}
__device__ __forceinline__ void ldsm4(uint32_t* r, uint32_t addr) {
    asm volatile("ldmatrix.sync.aligned.m8n8.x4.shared.b16 {%0,%1,%2,%3}, [%4];"
                 : "=r"(r[0]), "=r"(r[1]), "=r"(r[2]), "=r"(r[3]) : "r"(addr));
}
__device__ __forceinline__ void ldsm2(uint32_t* r, uint32_t addr) {
    asm volatile("ldmatrix.sync.aligned.m8n8.x2.shared.b16 {%0,%1}, [%2];"
                 : "=r"(r[0]), "=r"(r[1]) : "r"(addr));
}
__device__ __forceinline__ void mma16816(float* d, const uint32_t* a,
                                         uint32_t b0, uint32_t b1) {
    asm volatile(
        "mma.sync.aligned.m16n8k16.row.col.f32.bf16.bf16.f32 "
        "{%0,%1,%2,%3}, {%4,%5,%6,%7}, {%8,%9}, {%0,%1,%2,%3};"
        : "+f"(d[0]), "+f"(d[1]), "+f"(d[2]), "+f"(d[3])
        : "r"(a[0]), "r"(a[1]), "r"(a[2]), "r"(a[3]), "r"(b0), "r"(b1));
}
__device__ __forceinline__ void imma32(int* d, const uint32_t* a,
                                       uint32_t b0, uint32_t b1) {
    asm volatile(
        "mma.sync.aligned.m16n8k32.row.col.s32.s8.s8.s32 "
        "{%0,%1,%2,%3}, {%4,%5,%6,%7}, {%8,%9}, {%0,%1,%2,%3};"
        : "+r"(d[0]), "+r"(d[1]), "+r"(d[2]), "+r"(d[3])
        : "r"(a[0]), "r"(a[1]), "r"(a[2]), "r"(a[3]), "r"(b0), "r"(b1));
}
#define MBAR_WAIT(mbar, ph) do {                                              \
    asm volatile(                                                             \
        "{\n\t.reg .pred P1;\n\t"                                             \
        "W_%=:\n\t"                                                           \
        "mbarrier.try_wait.parity.acquire.cta.shared::cta.b64 P1, [%0], %1, 0x989680;\n\t" \
        "@P1 bra D_%=;\n\t"                                                   \
        "bra.uni W_%=;\n\t"                                                   \
        "D_%=:\n\t}"                                                          \
        :: "r"(mbar), "r"((unsigned)(ph)) : "memory");                        \
} while (0)

// ================== HMMA 128x128 tile body (shared by both GEMM users) ========
#define KC 32
#define GSTR2 40
#define SMAT2 (128 * GSTR2)
#define GEMM_SMEM (2 * 4 * SMAT2 * 2)

__device__ __forceinline__ void hmma_tile_body(
    const __nv_bfloat16* __restrict__ Ah, const __nv_bfloat16* __restrict__ Al,
    const __nv_bfloat16* __restrict__ Bh, const __nv_bfloat16* __restrict__ Bl,
    const float* __restrict__ bias, float* __restrict__ C,
    int m0, int n0, int ncol, char* smemc)
{
    const uint32_t sbase = s2u(smemc);
    const int tid  = threadIdx.x;
    const int wid  = tid >> 5;
    const int lane = tid & 31;
    const int wm   = wid & 3;
    const int wn   = wid >> 2;

    const uint32_t loff = (uint32_t)((lane & 15) * GSTR2 + ((lane >> 4) << 3));

    float acc[2][8][4];
#pragma unroll
    for (int i = 0; i < 2; i++)
#pragma unroll
        for (int j = 0; j < 8; j++)
#pragma unroll
            for (int q = 0; q < 4; q++) acc[i][j][q] = 0.0f;

    auto load_chunk = [&](int kc, int buf) {
        const __nv_bfloat16* gsrc[4] = {
            Ah + (size_t)m0 * H_ + kc * KC,
            Al + (size_t)m0 * H_ + kc * KC,
            Bh + (size_t)n0 * H_ + kc * KC,
            Bl + (size_t)n0 * H_ + kc * KC };
#pragma unroll
        for (int mat = 0; mat < 4; mat++) {
            const __nv_bfloat16* g = gsrc[mat];
            const uint32_t mb = sbase + 2u * ((buf * 4 + mat) * SMAT2);
#pragma unroll
            for (int p = 0; p < 2; p++) {
                int idx = tid + p * 256;
                int row = idx >> 2, unit = idx & 3;
                cpa16(mb + 2u * (row * GSTR2 + unit * 8),
                      g + (size_t)row * H_ + unit * 8);
            }
        }
    };

    load_chunk(0, 0);
    asm volatile("cp.async.commit_group;");

    for (int kc = 0; kc < 32; kc++) {
        const int buf = kc & 1;
        if (kc < 31) {
            load_chunk(kc + 1, buf ^ 1);
            asm volatile("cp.async.commit_group;");
            asm volatile("cp.async.wait_group 1;");
        } else {
            asm volatile("cp.async.wait_group 0;");
        }
        __syncthreads();

        const uint32_t bAh = sbase + 2u * ((buf * 4 + 0) * SMAT2);
        const uint32_t bAl = sbase + 2u * ((buf * 4 + 1) * SMAT2);
        const uint32_t bBh = sbase + 2u * ((buf * 4 + 2) * SMAT2);
        const uint32_t bBl = sbase + 2u * ((buf * 4 + 3) * SMAT2);

#pragma unroll
        for (int ks = 0; ks < 2; ks++) {
            const uint32_t coff = 2u * (ks * 16) + 2u * loff;
            uint32_t aH[2][4], aL[2][4], bH[4][4], bL[4][4];
#pragma unroll
            for (int im = 0; im < 2; im++) {
                uint32_t ro = 2u * ((wm * 32 + im * 16) * GSTR2);
                ldsm4(aH[im], bAh + ro + coff);
                ldsm4(aL[im], bAl + ro + coff);
            }
#pragma unroll
            for (int ib = 0; ib < 4; ib++) {
                uint32_t ro = 2u * ((wn * 64 + ib * 16) * GSTR2);
                ldsm4(bH[ib], bBh + ro + coff);
                ldsm4(bL[ib], bBl + ro + coff);
            }
#pragma unroll
            for (int im = 0; im < 2; im++)
#pragma unroll
                for (int ib = 0; ib < 4; ib++)
#pragma unroll
                    for (int hf = 0; hf < 2; hf++) {
                        float* d = acc[im][ib * 2 + hf];
                        mma16816(d, aH[im], bH[ib][hf], bH[ib][hf + 2]);
                        mma16816(d, aH[im], bL[ib][hf], bL[ib][hf + 2]);
                        mma16816(d, aL[im], bH[ib][hf], bH[ib][hf + 2]);
                    }
        }
        __syncthreads();
    }

#pragma unroll
    for (int im = 0; im < 2; im++) {
        const int mg = m0 + wm * 32 + im * 16 + (lane >> 2);
#pragma unroll
        for (int nb = 0; nb < 8; nb++) {
            const int ng = ncol + wn * 64 + nb * 8 + (lane & 3) * 2;
            const float bx = bias[ng], by = bias[ng + 1];
            float2 o0, o1;
            o0.x = acc[im][nb][0] + bx; o0.y = acc[im][nb][1] + by;
            o1.x = acc[im][nb][2] + bx; o1.y = acc[im][nb][3] + by;
            *reinterpret_cast<float2*>(C + (size_t)mg * 1024 + ng)       = o0;
            *reinterpret_cast<float2*>(C + (size_t)(mg + 8) * 1024 + ng) = o1;
        }
    }
}

// ================== input projection kernel (full device) ======================
struct ProjOut { const float* b[3]; float* c[3]; };

__global__ __launch_bounds__(256, 2)
void hmma_gemm3_kernel(const __nv_bfloat16* __restrict__ Ah,
                       const __nv_bfloat16* __restrict__ Al,
                       const __nv_bfloat16* __restrict__ Bh,
                       const __nv_bfloat16* __restrict__ Bl,
                       ProjOut po)
{
    extern __shared__ char smx[];
    const int nt = blockIdx.x, mt = blockIdx.y;
    const int sel  = nt >> 3;
    const int ncol = (nt & 7) * 128;
    hmma_tile_body(Ah, Al, Bh, Bl, po.b[sel], po.c[sel],
                   mt * 128, nt * 128, ncol, smx);
}

// ================== grid barrier (no L1 flush) =================================
__device__ __forceinline__ void grid_sync(unsigned int target) {
    __syncthreads();
    if (threadIdx.x == 0) {
        asm volatile("red.release.gpu.global.add.u32 [%0], 1;"
                     :: "l"(&g_bar_cnt) : "memory");
        unsigned int v;
        do {
            asm volatile("ld.acquire.gpu.global.u32 %0, [%1];"
                         : "=r"(v) : "l"(&g_bar_cnt) : "memory");
        } while (v < target);
    }
    __syncthreads();
}

// ================== MEGA kernel: recurrence (bid<128) + output proj ============
#define SW1A 0
#define SW0A 16384
#define SW1B 32768
#define SW0B 40960
#define SH1  49152
#define SH0  114688
#define MBOF 180224
#define REDOF 180288
#define RSMEM (180288 + 6144)
#define S_HI (1.0f / 65536.0f)
#define S_MID (1.0f / 16777216.0f)

__global__ __launch_bounds__(256, 1) void gru_mega_kernel(
    float* __restrict__ states, float* __restrict__ outputs,
    const float* __restrict__ b_q)
{
    extern __shared__ char smc[];
    int8_t* sm8 = reinterpret_cast<int8_t*>(smc);
    const int bid = blockIdx.x;

    // =================== output-projection blocks ===================
    if (bid >= NBLK) {
        const int ob = bid - NBLK;
        const int mt = ob >> 3;
        const int nt = ob & 7;
        // wait for timesteps 2mt, 2mt+1 to be complete
        if (threadIdx.x == 0) {
            const unsigned target = (unsigned)(4 * mt + 4) * NBLK;
            unsigned v;
            do {
                asm volatile("ld.acquire.gpu.global.u32 %0, [%1];"
                             : "=r"(v) : "l"(&g_bar_cnt) : "memory");
            } while (v < target);
        }
        __syncthreads();
        hmma_tile_body(g_Sh, g_Sl, g_Bh[3], g_Bl[3], b_q, outputs,
                       mt * 128, nt * 128, nt * 128, smc);
        return;
    }

    // =================== recurrence blocks ===================
    const uint32_t sbase = s2u(sm8);
    const uint32_t mb0 = sbase + MBOF;

    const int tid  = threadIdx.x;
    const int wid  = tid >> 5;
    const int lane = tid & 31;

    const int a_n0 = bid * 16;
    const int a_wm = wid & 3, a_wn = wid >> 2;
    const int b_n0 = bid * 8;

    const uint32_t rA_a = (uint32_t)(a_wm * 16 + (lane & 15));
    const uint32_t selA = (uint32_t)(lane >> 4);
    const uint32_t rB_a = (uint32_t)(a_wn * 8 + (lane & 7));
    const uint32_t selB = (uint32_t)((lane >> 3) & 1);
    const uint32_t rA_b = (uint32_t)((wid & 3) * 16 + (lane & 15));
    const uint32_t rB_b = (uint32_t)(lane & 7);

    if (tid == 0) {
#pragma unroll
        for (int c = 0; c < 4; c++)
            asm volatile("mbarrier.init.shared.b64 [%0], 1;"
                         :: "r"(mb0 + c * 8) : "memory");
    }
    {
        const int8_t* W1A = g_w1RU + (size_t)a_n0 * 1024;
        const int8_t* W0A = g_w0RU + (size_t)a_n0 * 1024;
        const int8_t* W1B = g_w1C + (size_t)b_n0 * 1024;
        const int8_t* W0B = g_w0C + (size_t)b_n0 * 1024;
        for (int i = tid; i < 1024; i += 256) {
            uint32_t bo = (uint32_t)i * 16;
            cpa16(sbase + SW1A + bo, W1A + (size_t)i * 16);
            cpa16(sbase + SW0A + bo, W0A + (size_t)i * 16);
        }
        for (int i = tid; i < 512; i += 256) {
            uint32_t bo = (uint32_t)i * 16;
            cpa16(sbase + SW1B + bo, W1B + (size_t)i * 16);
            cpa16(sbase + SW0B + bo, W0B + (size_t)i * 16);
        }
        asm volatile("cp.async.commit_group;");
        asm volatile("cp.async.wait_group 0;");
    }
    __syncthreads();

    unsigned int epoch = 0;
    int par = 0;

    for (int t = 0; t < T_; t++) {
        const size_t xbase = (size_t)t * B_ * H_;

        // ======================= phase A: gates ===============================
        {
            const int gc = a_n0 + a_wn * 8 + (lane & 3) * 2;
            const int xc = gc & (H_ - 1);
            const float* xp = (bid < 64) ? g_x[0] : g_x[1];
            float2 xv[2], hv[2];
#pragma unroll
            for (int i = 0; i < 2; i++) {
                const int row = a_wm * 16 + (lane >> 2) + i * 8;
                const size_t off = (size_t)row * H_ + xc;
                xv[i] = __ldcg(reinterpret_cast<const float2*>(xp + xbase + off));
                if (bid < 64)
                    hv[i] = __ldcg(reinterpret_cast<const float2*>(g_h + off));
            }
            if (tid == 0) {
#pragma unroll
                for (int c = 0; c < 4; c++) {
                    asm volatile("mbarrier.arrive.expect_tx.shared.b64 _, [%0], %1;"
                                 :: "r"(mb0 + c * 8), "r"(32768u) : "memory");
                    bulk_g2s(sbase + SH1 + c * 16384, g_h1 + c * 16384, 16384u, mb0 + c * 8);
                    bulk_g2s(sbase + SH0 + c * 16384, g_h0 + c * 16384, 16384u, mb0 + c * 8);
                }
            }
            MBAR_WAIT(mb0 + a_wm * 8, par);

            int dhi[4] = {0,0,0,0}, dmA[4] = {0,0,0,0}, dmB[4] = {0,0,0,0};
            const uint32_t baseA1 = sbase + SH1 + rA_a * 1024;
            const uint32_t baseA0 = sbase + SH0 + rA_a * 1024;
            const uint32_t baseB1 = sbase + SW1A + rB_a * 1024;
            const uint32_t baseB0 = sbase + SW0A + rB_a * 1024;
            const uint32_t swA = rA_a & 7, swB = rB_a & 7;
#pragma unroll 8
            for (int ks = 0; ks < 32; ks++) {
                const uint32_t uA = (((uint32_t)ks * 2 + selA) ^ swA) << 4;
                const uint32_t uB = (((uint32_t)ks * 2 + selB) ^ swB) << 4;
                uint32_t a1[4], a0[4], b1[2], b0[2];
                ldsm4(a1, baseA1 + uA);
                ldsm4(a0, baseA0 + uA);
                ldsm2(b1, baseB1 + uB);
                ldsm2(b0, baseB0 + uB);
                imma32(dhi, a1, b1[0], b1[1]);
                imma32(dmA, a1, b0[0], b0[1]);
                imma32(dmB, a0, b1[0], b1[1]);
            }

            // epilogue A
#pragma unroll
            for (int i = 0; i < 2; i++) {
                const int row = a_wm * 16 + (lane >> 2) + i * 8;
                const size_t off = (size_t)row * H_ + xc;
                float z0 = (float)dhi[2*i+0] * S_HI
                         + (float)(dmA[2*i+0] + dmB[2*i+0]) * S_MID + xv[i].x;
                float z1 = (float)dhi[2*i+1] * S_HI
                         + (float)(dmA[2*i+1] + dmB[2*i+1]) * S_MID + xv[i].y;
                float s0 = 1.0f / (1.0f + __expf(-z0));
                float s1 = 1.0f / (1.0f + __expf(-z1));
                if (bid < 64) {
                    float v0 = hv[i].x * s0, v1 = hv[i].y * s1;
                    int q0 = __float2int_rn(v0 * 16384.0f);
                    int q1 = __float2int_rn(v1 * 16384.0f);
                    int p0 = (q0 + 128) >> 8, p1 = (q1 + 128) >> 8;
                    int r0 = q0 - (p0 << 8), r1 = q1 - (p1 << 8);
                    unsigned short hi2 = (unsigned short)((p0 & 0xFF) | ((p1 & 0xFF) << 8));
                    unsigned short lo2 = (unsigned short)((r0 & 0xFF) | ((r1 & 0xFF) << 8));
                    size_t sa = (size_t)row * 1024 +
                                ((((xc >> 4) ^ (row & 7)) << 4) | (xc & 15));
                    __stcg(reinterpret_cast<unsigned short*>(g_hR1 + sa), hi2);
                    __stcg(reinterpret_cast<unsigned short*>(g_hR0 + sa), lo2);
                } else {
                    __stcg(reinterpret_cast<float2*>(g_U + off), make_float2(s0, s1));
                }
            }
        }
        par ^= 1;
        epoch++;
        grid_sync(epoch * NBLK);

        // ================= phase B: candidate + update ========================
        {
            const int gc = b_n0 + (lane & 3) * 2;
            float2 xv[2], uv[2], hv[2];
            if (wid < 4) {
#pragma unroll
                for (int i = 0; i < 2; i++) {
                    const int row = wid * 16 + (lane >> 2) + i * 8;
                    const size_t off = (size_t)row * H_ + gc;
                    xv[i] = __ldcg(reinterpret_cast<const float2*>(g_x[2] + xbase + off));
                    uv[i] = __ldcg(reinterpret_cast<const float2*>(g_U + off));
                    hv[i] = __ldcg(reinterpret_cast<const float2*>(g_h + off));
                }
            }
            if (tid == 0) {
#pragma unroll
                for (int c = 0; c < 4; c++) {
                    asm volatile("mbarrier.arrive.expect_tx.shared.b64 _, [%0], %1;"
                                 :: "r"(mb0 + c * 8), "r"(32768u) : "memory");
                    bulk_g2s(sbase + SH1 + c * 16384, g_hR1 + c * 16384, 16384u, mb0 + c * 8);
                    bulk_g2s(sbase + SH0 + c * 16384, g_hR0 + c * 16384, 16384u, mb0 + c * 8);
                }
            }
            MBAR_WAIT(mb0 + (wid & 3) * 8, par);

            int dhi[4] = {0,0,0,0}, dmA[4] = {0,0,0,0}, dmB[4] = {0,0,0,0};
            {
                const uint32_t baseA1 = sbase + SH1 + rA_b * 1024;
                const uint32_t baseA0 = sbase + SH0 + rA_b * 1024;
                const uint32_t baseB1 = sbase + SW1B + rB_b * 1024;
                const uint32_t baseB0 = sbase + SW0B + rB_b * 1024;
                const uint32_t swA = rA_b & 7, swB = rB_b & 7;
                const int ks0 = (wid >> 2) * 16;
#pragma unroll 8
                for (int ks = ks0; ks < ks0 + 16; ks++) {
                    const uint32_t uA = (((uint32_t)ks * 2 + selA) ^ swA) << 4;
                    const uint32_t uB = (((uint32_t)ks * 2 + selB) ^ swB) << 4;
                    uint32_t a1[4], a0[4], b1[2], b0[2];
                    ldsm4(a1, baseA1 + uA);
                    ldsm4(a0, baseA0 + uA);
                    ldsm2(b1, baseB1 + uB);
                    ldsm2(b0, baseB0 + uB);
                    imma32(dhi, a1, b1[0], b1[1]);
                    imma32(dmA, a1, b0[0], b0[1]);
                    imma32(dmB, a0, b1[0], b1[1]);
                }
            }
            if (wid >= 4) {
                int* rb = reinterpret_cast<int*>(sm8 + REDOF)
                          + (((wid - 4) * 32 + lane) * 12);
#pragma unroll
                for (int j = 0; j < 4; j++) { rb[j] = dhi[j]; rb[4 + j] = dmA[j]; rb[8 + j] = dmB[j]; }
            }
            __syncthreads();
            if (wid < 4) {
                const int* rb = reinterpret_cast<const int*>(sm8 + REDOF)
                                + ((wid * 32 + lane) * 12);
#pragma unroll
                for (int j = 0; j < 4; j++) { dhi[j] += rb[j]; dmA[j] += rb[4 + j]; dmB[j] += rb[8 + j]; }

#pragma unroll
                for (int i = 0; i < 2; i++) {
                    const int row = wid * 16 + (lane >> 2) + i * 8;
                    const size_t off = (size_t)row * H_ + gc;
                    float z0 = (float)dhi[2*i+0] * S_HI
                             + (float)(dmA[2*i+0] + dmB[2*i+0]) * S_MID + xv[i].x;
                    float z1 = (float)dhi[2*i+1] * S_HI
                             + (float)(dmA[2*i+1] + dmB[2*i+1]) * S_MID + xv[i].y;
                    float hc0 = tanhf(z0), hc1 = tanhf(z1);
                    float hn0 = uv[i].x * hv[i].x + (1.0f - uv[i].x) * hc0;
                    float hn1 = uv[i].y * hv[i].y + (1.0f - uv[i].y) * hc1;
                    __stcg(reinterpret_cast<float2*>(g_h + off), make_float2(hn0, hn1));
                    __stcg(reinterpret_cast<float2*>(states + xbase + off),
                           make_float2(hn0, hn1));
                    // bf16 split of states for the (overlapped) output projection
                    __nv_bfloat16 b0 = __float2bfloat16(hn0);
                    __nv_bfloat16 b1 = __float2bfloat16(hn1);
                    unsigned short u0 = *reinterpret_cast<unsigned short*>(&b0);
                    unsigned short u1 = *reinterpret_cast<unsigned short*>(&b1);
                    __nv_bfloat16 l0 = __float2bfloat16(hn0 - __bfloat162float(b0));
                    __nv_bfloat16 l1 = __float2bfloat16(hn1 - __bfloat162float(b1));
                    unsigned short v0 = *reinterpret_cast<unsigned short*>(&l0);
                    unsigned short v1 = *reinterpret_cast<unsigned short*>(&l1);
                    __stcg(reinterpret_cast<unsigned int*>(g_Sh + xbase + off),
                           ((unsigned)u1 << 16) | u0);
                    __stcg(reinterpret_cast<unsigned int*>(g_Sl + xbase + off),
                           ((unsigned)v1 << 16) | v0);
                    int q0 = __float2int_rn(hn0 * 16384.0f);
                    int q1 = __float2int_rn(hn1 * 16384.0f);
                    int p0 = (q0 + 128) >> 8, p1 = (q1 + 128) >> 8;
                    int r0 = q0 - (p0 << 8), r1 = q1 - (p1 << 8);
                    unsigned short hi2 = (unsigned short)((p0 & 0xFF) | ((p1 & 0xFF) << 8));
                    unsigned short lo2 = (unsigned short)((r0 & 0xFF) | ((r1 & 0xFF) << 8));
                    size_t sa = (size_t)row * 1024 +
                                ((((gc >> 4) ^ (row & 7)) << 4) | (gc & 15));
                    __stcg(reinterpret_cast<unsigned short*>(g_h1 + sa), hi2);
                    __stcg(reinterpret_cast<unsigned short*>(g_h0 + sa), lo2);
                }
            }
        }
        par ^= 1;
        epoch++;
        grid_sync(epoch * NBLK);
    }
}

// ================== launcher ===================================================
extern "C" void kernel_launch(void* const* d_in, const int* in_sizes, int n_in,
                              void* d_out, int out_size)
{
    const float* X    = (const float*)d_in[0];
    const float* W_xr = (const float*)d_in[1];
    const float* W_xu = (const float*)d_in[2];
    const float* W_xh = (const float*)d_in[3];
    const float* W_hr = (const float*)d_in[4];
    const float* W_hu = (const float*)d_in[5];
    const float* W_hh = (const float*)d_in[6];
    const float* b_r  = (const float*)d_in[7];
    const float* b_u  = (const float*)d_in[8];
    const float* b_h  = (const float*)d_in[9];
    const float* W_hq = (const float*)d_in[10];
    const float* b_q  = (const float*)d_in[11];

    float* out     = (float*)d_out;
    float* outputs = out;                        // [T,B,O]
    float* states  = out + (size_t)TB_ * O_;     // [T,B,H]

    void *p_x, *p_ah, *p_al, *p_bh, *p_bl;
    cudaGetSymbolAddress(&p_x, g_x);
    cudaGetSymbolAddress(&p_ah, g_Ah);
    cudaGetSymbolAddress(&p_al, g_Al);
    cudaGetSymbolAddress(&p_bh, g_Bh);
    cudaGetSymbolAddress(&p_bl, g_Bl);

    float* xbuf = (float*)p_x;
    __nv_bfloat16* Ah = (__nv_bfloat16*)p_ah;
    __nv_bfloat16* Al = (__nv_bfloat16*)p_al;
    __nv_bfloat16* Bh = (__nv_bfloat16*)p_bh;
    __nv_bfloat16* Bl = (__nv_bfloat16*)p_bl;

    static int smem_set = 0;
    if (!smem_set) {
        cudaFuncSetAttribute(hmma_gemm3_kernel,
                             cudaFuncAttributeMaxDynamicSharedMemorySize, GEMM_SMEM);
        cudaFuncSetAttribute(gru_mega_kernel,
                             cudaFuncAttributeMaxDynamicSharedMemorySize, RSMEM);
        smem_set = 1;
    }

    // 0: fused prep
    prep_all<<<61696, 256>>>(X, W_xr, W_xu, W_xh, W_hq, W_hr, W_hu, W_hh);
    // 1: fused input projections (full device)
    {
        ProjOut po;
        po.b[0] = b_r; po.b[1] = b_u; po.b[2] = b_h;
        po.c[0] = xbuf; po.c[1] = xbuf + (size_t)TB_ * H_; po.c[2] = xbuf + 2 * (size_t)TB_ * H_;
        dim3 gg(24, TB_ / 128);
        hmma_gemm3_kernel<<<gg, 256, GEMM_SMEM>>>(Ah, Al, Bh, Bl, po);
    }
    // 2: mega kernel — recurrence (128 blocks) + overlapped output projection
    gru_mega_kernel<<<NBLK + 2048, 256, RSMEM>>>(states, outputs, b_q);
}

// round 15
// speedup vs baseline: 1.1470x; 1.0525x over previous
#include <cuda_runtime.h>
#include <cuda_bf16.h>
#include <stdint.h>
#include <math.h>

#define T_ 512
#define B_ 64
#define I_ 1024
#define H_ 1024
#define O_ 1024
#define TB_ (T_ * B_)
#define NBLK 128
#define NOUT_TILES 2048

// ================== scratch (device globals; no allocations) ==================
__device__ float g_x[3][TB_ * H_];         // xr, xu, xh projections
__device__ float g_h [B_ * H_];            // hidden state fp32
__device__ float g_U [B_ * H_];            // update gate fp32
__device__ unsigned int g_barA[4];         // per-row-group phase A arrivals
__device__ unsigned int g_barB[4];         // per-row-group phase B arrivals
__device__ unsigned int g_tile_ctr;        // output-projection work queue

// int8 dual-plane mirrors, SWIZZLED: addr(r,k) = r*1024 + (((k>>4)^(r&7))<<4) + (k&15)
__device__ int8_t g_h1 [B_ * H_];
__device__ int8_t g_h0 [B_ * H_];
__device__ int8_t g_hR1[B_ * H_];
__device__ int8_t g_hR0[B_ * H_];
__device__ int8_t g_w1RU[2 * H_ * H_];
__device__ int8_t g_w0RU[2 * H_ * H_];
__device__ int8_t g_w1C[H_ * H_];
__device__ int8_t g_w0C[H_ * H_];

// bf16 split operands
__device__ __nv_bfloat16 g_Ah[TB_ * H_];   // X hi/lo
__device__ __nv_bfloat16 g_Al[TB_ * H_];
__device__ __nv_bfloat16 g_Sh[TB_ * H_];   // states hi/lo
__device__ __nv_bfloat16 g_Sl[TB_ * H_];
__device__ __nv_bfloat16 g_Bh[4][H_ * H_];
__device__ __nv_bfloat16 g_Bl[4][H_ * H_];

// ================== fused prep =================================================
__global__ __launch_bounds__(256) void prep_all(
    const float* __restrict__ X,
    const float* __restrict__ Wxr, const float* __restrict__ Wxu,
    const float* __restrict__ Wxh, const float* __restrict__ Whq,
    const float* __restrict__ Whr, const float* __restrict__ Whu,
    const float* __restrict__ Whh)
{
    const int b = blockIdx.x;
    const int tid = threadIdx.x;
    if (b < 32768) {
        size_t i4 = ((size_t)b * 256 + tid) * 4;
        float4 v = *reinterpret_cast<const float4*>(X + i4);
        float vv[4] = {v.x, v.y, v.z, v.w};
        __align__(8) __nv_bfloat16 hb[4], lb[4];
#pragma unroll
        for (int j = 0; j < 4; j++) {
            __nv_bfloat16 h = __float2bfloat16(vv[j]);
            hb[j] = h;
            lb[j] = __float2bfloat16(vv[j] - __bfloat162float(h));
        }
        *reinterpret_cast<uint2*>(g_Ah + i4) = *reinterpret_cast<const uint2*>(hb);
        *reinterpret_cast<uint2*>(g_Al + i4) = *reinterpret_cast<const uint2*>(lb);
    } else if (b < 49152) {
        int bb = b - 32768;
        int which = bb >> 12;
        int idx = (bb & 4095) * 256 + tid;
        const float* W = which == 0 ? Wxr : which == 1 ? Wxu : which == 2 ? Wxh : Whq;
        int k = idx >> 10, n = idx & (H_ - 1);
        float v = W[idx];
        __nv_bfloat16 h = __float2bfloat16(v);
        __nv_bfloat16 l = __float2bfloat16(v - __bfloat162float(h));
        g_Bh[which][(size_t)n * H_ + k] = h;
        g_Bl[which][(size_t)n * H_ + k] = l;
    } else if (b < 61440) {
        int bb = b - 49152;
        int which = bb >> 12;
        int idx = (bb & 4095) * 256 + tid;
        const float* W = which == 0 ? Whr : which == 1 ? Whu : Whh;
        int8_t* p1 = which == 0 ? g_w1RU : which == 1 ? g_w1RU + (size_t)H_ * H_ : g_w1C;
        int8_t* p0 = which == 0 ? g_w0RU : which == 1 ? g_w0RU + (size_t)H_ * H_ : g_w0C;
        int k = idx >> 10, n = idx & (H_ - 1);
        float v = W[idx];
        int q = __float2int_rn(v * 262144.0f);
        q = max(-32640, min(32639, q));
        int w1 = (q + 128) >> 8;
        int w0 = q - (w1 << 8);
        size_t addr = (size_t)n * 1024 + ((((k >> 4) ^ (n & 7)) << 4) | (k & 15));
        p1[addr] = (int8_t)w1;
        p0[addr] = (int8_t)w0;
    } else {
        int i = (b - 61440) * 256 + tid;
        if (i == 0) {
            g_tile_ctr = 0;
#pragma unroll
            for (int g = 0; g < 4; g++) { g_barA[g] = 0; g_barB[g] = 0; }
        }
        if (i < B_ * H_) {
            g_h[i] = 0.0f;
            g_h1[i] = 0;
            g_h0[i] = 0;
        }
    }
}

// ================== PTX helpers ================================================
__device__ __forceinline__ uint32_t s2u(const void* p) {
    uint32_t a;
    asm("{ .reg .u64 t; cvta.to.shared.u64 t, %1; cvt.u32.u64 %0, t; }"
        : "=r"(a) : "l"(p));
    return a;
}
__device__ __forceinline__ void cpa16(uint32_t saddr, const void* g) {
    asm volatile("cp.async.cg.shared.global [%0], [%1], 16;"
                 :: "r"(saddr), "l"(g));
}
__device__ __forceinline__ void bulk_g2s(uint32_t saddr, const void* g,
                                         uint32_t bytes, uint32_t mbar) {
    asm volatile(
        "cp.async.bulk.shared::cluster.global.mbarrier::complete_tx::bytes "
        "[%0], [%1], %2, [%3];"
        :: "r"(saddr), "l"(g), "r"(bytes), "r"(mbar) : "memory");
}
__device__ __forceinline__ void ldsm4(uint32_t* r, uint32_t addr) {
    asm volatile("ldmatrix.sync.aligned.m8n8.x4.shared.b16 {%0,%1,%2,%3}, [%4];"
                 : "=r"(r[0]), "=r"(r[1]), "=r"(r[2]), "=r"(r[3]) : "r"(addr));
}
__device__ __forceinline__ void ldsm2(uint32_t* r, uint32_t addr) {
    asm volatile("ldmatrix.sync.aligned.m8n8.x2.shared.b16 {%0,%1}, [%2];"
                 : "=r"(r[0]), "=r"(r[1]) : "r"(addr));
}
__device__ __forceinline__ void mma16816(float* d, const uint32_t* a,
                                         uint32_t b0, uint32_t b1) {
    asm volatile(
        "mma.sync.aligned.m16n8k16.row.col.f32.bf16.bf16.f32 "
        "{%0,%1,%2,%3}, {%4,%5,%6,%7}, {%8,%9}, {%0,%1,%2,%3};"
        : "+f"(d[0]), "+f"(d[1]), "+f"(d[2]), "+f"(d[3])
        : "r"(a[0]), "r"(a[1]), "r"(a[2]), "r"(a[3]), "r"(b0), "r"(b1));
}
__device__ __forceinline__ void imma32(int* d, const uint32_t* a,
                                       uint32_t b0, uint32_t b1) {
    asm volatile(
        "mma.sync.aligned.m16n8k32.row.col.s32.s8.s8.s32 "
        "{%0,%1,%2,%3}, {%4,%5,%6,%7}, {%8,%9}, {%0,%1,%2,%3};"
        : "+r"(d[0]), "+r"(d[1]), "+r"(d[2]), "+r"(d[3])
        : "r"(a[0]), "r"(a[1]), "r"(a[2]), "r"(a[3]), "r"(b0), "r"(b1));
}
#define MBAR_WAIT(mbar, ph) do {                                              \
    asm volatile(                                                             \
        "{\n\t.reg .pred P1;\n\t"                                             \
        "W_%=:\n\t"                                                           \
        "mbarrier.try_wait.parity.acquire.cta.shared::cta.b64 P1, [%0], %1, 0x989680;\n\t" \
        "@P1 bra D_%=;\n\t"                                                   \
        "bra.uni W_%=;\n\t"                                                   \
        "D_%=:\n\t}"                                                          \
        :: "r"(mbar), "r"((unsigned)(ph)) : "memory");                        \
} while (0)

// ================== HMMA 128x128 tile body =====================================
#define KC 32
#define GSTR2 40
#define SMAT2 (128 * GSTR2)
#define GEMM_SMEM (2 * 4 * SMAT2 * 2)

__device__ __forceinline__ void hmma_tile_body(
    const __nv_bfloat16* __restrict__ Ah, const __nv_bfloat16* __restrict__ Al,
    const __nv_bfloat16* __restrict__ Bh, const __nv_bfloat16* __restrict__ Bl,
    const float* __restrict__ bias, float* __restrict__ C,
    int m0, int n0, int ncol, char* smemc)
{
    const uint32_t sbase = s2u(smemc);
    const int tid  = threadIdx.x;
    const int wid  = tid >> 5;
    const int lane = tid & 31;
    const int wm   = wid & 3;
    const int wn   = wid >> 2;

    const uint32_t loff = (uint32_t)((lane & 15) * GSTR2 + ((lane >> 4) << 3));

    float acc[2][8][4];
#pragma unroll
    for (int i = 0; i < 2; i++)
#pragma unroll
        for (int j = 0; j < 8; j++)
#pragma unroll
            for (int q = 0; q < 4; q++) acc[i][j][q] = 0.0f;

    auto load_chunk = [&](int kc, int buf) {
        const __nv_bfloat16* gsrc[4] = {
            Ah + (size_t)m0 * H_ + kc * KC,
            Al + (size_t)m0 * H_ + kc * KC,
            Bh + (size_t)n0 * H_ + kc * KC,
            Bl + (size_t)n0 * H_ + kc * KC };
#pragma unroll
        for (int mat = 0; mat < 4; mat++) {
            const __nv_bfloat16* g = gsrc[mat];
            const uint32_t mb = sbase + 2u * ((buf * 4 + mat) * SMAT2);
#pragma unroll
            for (int p = 0; p < 2; p++) {
                int idx = tid + p * 256;
                int row = idx >> 2, unit = idx & 3;
                cpa16(mb + 2u * (row * GSTR2 + unit * 8),
                      g + (size_t)row * H_ + unit * 8);
            }
        }
    };

    load_chunk(0, 0);
    asm volatile("cp.async.commit_group;");

    for (int kc = 0; kc < 32; kc++) {
        const int buf = kc & 1;
        if (kc < 31) {
            load_chunk(kc + 1, buf ^ 1);
            asm volatile("cp.async.commit_group;");
            asm volatile("cp.async.wait_group 1;");
        } else {
            asm volatile("cp.async.wait_group 0;");
        }
        __syncthreads();

        const uint32_t bAh = sbase + 2u * ((buf * 4 + 0) * SMAT2);
        const uint32_t bAl = sbase + 2u * ((buf * 4 + 1) * SMAT2);
        const uint32_t bBh = sbase + 2u * ((buf * 4 + 2) * SMAT2);
        const uint32_t bBl = sbase + 2u * ((buf * 4 + 3) * SMAT2);

#pragma unroll
        for (int ks = 0; ks < 2; ks++) {
            const uint32_t coff = 2u * (ks * 16) + 2u * loff;
            uint32_t aH[2][4], aL[2][4], bH[4][4], bL[4][4];
#pragma unroll
            for (int im = 0; im < 2; im++) {
                uint32_t ro = 2u * ((wm * 32 + im * 16) * GSTR2);
                ldsm4(aH[im], bAh + ro + coff);
                ldsm4(aL[im], bAl + ro + coff);
            }
#pragma unroll
            for (int ib = 0; ib < 4; ib++) {
                uint32_t ro = 2u * ((wn * 64 + ib * 16) * GSTR2);
                ldsm4(bH[ib], bBh + ro + coff);
                ldsm4(bL[ib], bBl + ro + coff);
            }
#pragma unroll
            for (int im = 0; im < 2; im++)
#pragma unroll
                for (int ib = 0; ib < 4; ib++)
#pragma unroll
                    for (int hf = 0; hf < 2; hf++) {
                        float* d = acc[im][ib * 2 + hf];
                        mma16816(d, aH[im], bH[ib][hf], bH[ib][hf + 2]);
                        mma16816(d, aH[im], bL[ib][hf], bL[ib][hf + 2]);
                        mma16816(d, aL[im], bH[ib][hf], bH[ib][hf + 2]);
                    }
        }
        __syncthreads();
    }

#pragma unroll
    for (int im = 0; im < 2; im++) {
        const int mg = m0 + wm * 32 + im * 16 + (lane >> 2);
#pragma unroll
        for (int nb = 0; nb < 8; nb++) {
            const int ng = ncol + wn * 64 + nb * 8 + (lane & 3) * 2;
            const float bx = bias[ng], by = bias[ng + 1];
            float2 o0, o1;
            o0.x = acc[im][nb][0] + bx; o0.y = acc[im][nb][1] + by;
            o1.x = acc[im][nb][2] + bx; o1.y = acc[im][nb][3] + by;
            *reinterpret_cast<float2*>(C + (size_t)mg * 1024 + ng)       = o0;
            *reinterpret_cast<float2*>(C + (size_t)(mg + 8) * 1024 + ng) = o1;
        }
    }
}

// ================== input projection kernel (full device) ======================
struct ProjOut { const float* b[3]; float* c[3]; };

__global__ __launch_bounds__(256, 2)
void hmma_gemm3_kernel(const __nv_bfloat16* __restrict__ Ah,
                       const __nv_bfloat16* __restrict__ Al,
                       const __nv_bfloat16* __restrict__ Bh,
                       const __nv_bfloat16* __restrict__ Bl,
                       ProjOut po)
{
    extern __shared__ char smx[];
    const int nt = blockIdx.x, mt = blockIdx.y;
    const int sel  = nt >> 3;
    const int ncol = (nt & 7) * 128;
    hmma_tile_body(Ah, Al, Bh, Bl, po.b[sel], po.c[sel],
                   mt * 128, nt * 128, ncol, smx);
}

// ================== group barrier primitives ===================================
__device__ __forceinline__ void grp_arrive(unsigned int* ctr) {
    __syncthreads();
    if (threadIdx.x == 0)
        asm volatile("red.release.gpu.global.add.u32 [%0], 1;"
                     :: "l"(ctr) : "memory");
}
__device__ __forceinline__ void grp_wait(unsigned int* ctr, unsigned int target) {
    if (threadIdx.x == 0) {
        unsigned int v;
        do {
            asm volatile("ld.acquire.gpu.global.u32 %0, [%1];"
                         : "=r"(v) : "l"(ctr) : "memory");
        } while (v < target);
    }
    __syncthreads();
}

// ================== MEGA kernel: 2-D partitioned recurrence + outproj queue ====
// smem: QW1A 0..64K (W_RU p1, 64 cols), QW0A 64K..128K, QW1B 128K..160K (W_C p1),
//       QW0B 160K..192K, QH1 192K..208K, QH0 208K..224K, mbar @224K.
#define QW1A 0
#define QW0A 65536
#define QW1B 131072
#define QW0B 163840
#define QH1  196608
#define QH0  212992
#define QMB  229376
#define QRED 196608            // reuse QH1 after MMA (phase B reduction)
#define RSMEM (229376 + 64)
#define S_HI (1.0f / 65536.0f)
#define S_MID (1.0f / 16777216.0f)

__global__ __launch_bounds__(256, 1) void gru_mega_kernel(
    float* __restrict__ states, float* __restrict__ outputs,
    const float* __restrict__ b_q)
{
    extern __shared__ char smc[];
    const int bid = blockIdx.x;
    const int tid = threadIdx.x;

    if (bid < NBLK) {
        // =================== recurrence block ===================
        const uint32_t sbase = s2u(smc);
        const uint32_t mb = sbase + QMB;
        const int wid  = tid >> 5;
        const int lane = tid & 31;

        const int rg = bid >> 5;           // row group 0..3
        const int cb = bid & 31;           // col block 0..31
        const int r0 = rg * 16;            // 16 batch rows
        const int gc0 = cb * 64;           // 64 combined [R|U] cols
        const int cc0 = cb * 32;           // 32 candidate cols

        // lane identities
        const uint32_t rA   = (uint32_t)(lane & 15);
        const uint32_t selA = (uint32_t)(lane >> 4);
        const uint32_t swA  = rA & 7;
        const uint32_t rBa  = (uint32_t)(wid * 8 + (lane & 7));       // phase A W row
        const uint32_t selB = (uint32_t)((lane >> 3) & 1);
        const uint32_t swBa = rBa & 7;
        const uint32_t rBb  = (uint32_t)((wid & 3) * 8 + (lane & 7)); // phase B W row
        const uint32_t swBb = rBb & 7;

        if (tid == 0)
            asm volatile("mbarrier.init.shared.b64 [%0], 1;" :: "r"(mb) : "memory");
        // resident weights
        {
            const int8_t* W1A = g_w1RU + (size_t)gc0 * 1024;
            const int8_t* W0A = g_w0RU + (size_t)gc0 * 1024;
            const int8_t* W1B = g_w1C + (size_t)cc0 * 1024;
            const int8_t* W0B = g_w0C + (size_t)cc0 * 1024;
            for (int i = tid; i < 4096; i += 256) {
                uint32_t bo = (uint32_t)i * 16;
                cpa16(sbase + QW1A + bo, W1A + (size_t)i * 16);
                cpa16(sbase + QW0A + bo, W0A + (size_t)i * 16);
            }
            for (int i = tid; i < 2048; i += 256) {
                uint32_t bo = (uint32_t)i * 16;
                cpa16(sbase + QW1B + bo, W1B + (size_t)i * 16);
                cpa16(sbase + QW0B + bo, W0B + (size_t)i * 16);
            }
            asm volatile("cp.async.commit_group;");
            asm volatile("cp.async.wait_group 0;");
        }
        __syncthreads();

        int par = 0;

        for (int t = 0; t < T_; t++) {
            const size_t xbase = (size_t)t * B_ * H_;
            const unsigned tgt = (unsigned)(t + 1) * 32;

            // ======= phase A: gates (16 rows x 64 combined cols) =======
            {
                const int gcomb = gc0 + wid * 8 + (lane & 3) * 2;
                const int xc = gcomb & (H_ - 1);
                const float* xp = (cb < 16) ? g_x[0] : g_x[1];
                float2 xv[2], hv[2];
#pragma unroll
                for (int i = 0; i < 2; i++) {
                    const int rowg = r0 + (lane >> 2) + i * 8;
                    const size_t off = (size_t)rowg * H_ + xc;
                    xv[i] = __ldcg(reinterpret_cast<const float2*>(xp + xbase + off));
                    if (cb < 16)
                        hv[i] = __ldcg(reinterpret_cast<const float2*>(g_h + off));
                }
                if (tid == 0) {
                    asm volatile("mbarrier.arrive.expect_tx.shared.b64 _, [%0], %1;"
                                 :: "r"(mb), "r"(32768u) : "memory");
                    bulk_g2s(sbase + QH1, g_h1 + (size_t)r0 * 1024, 16384u, mb);
                    bulk_g2s(sbase + QH0, g_h0 + (size_t)r0 * 1024, 16384u, mb);
                }
                MBAR_WAIT(mb, par);
                par ^= 1;

                int dhi[4] = {0,0,0,0}, dmA[4] = {0,0,0,0}, dmB[4] = {0,0,0,0};
                const uint32_t baseA1 = sbase + QH1 + rA * 1024;
                const uint32_t baseA0 = sbase + QH0 + rA * 1024;
                const uint32_t baseB1 = sbase + QW1A + rBa * 1024;
                const uint32_t baseB0 = sbase + QW0A + rBa * 1024;
#pragma unroll 8
                for (int ks = 0; ks < 32; ks++) {
                    const uint32_t uA = (((uint32_t)ks * 2 + selA) ^ swA) << 4;
                    const uint32_t uB = (((uint32_t)ks * 2 + selB) ^ swBa) << 4;
                    uint32_t a1[4], a0[4], b1[2], b0[2];
                    ldsm4(a1, baseA1 + uA);
                    ldsm4(a0, baseA0 + uA);
                    ldsm2(b1, baseB1 + uB);
                    ldsm2(b0, baseB0 + uB);
                    imma32(dhi, a1, b1[0], b1[1]);
                    imma32(dmA, a1, b0[0], b0[1]);
                    imma32(dmB, a0, b1[0], b1[1]);
                }

#pragma unroll
                for (int i = 0; i < 2; i++) {
                    const int rowg = r0 + (lane >> 2) + i * 8;
                    const size_t off = (size_t)rowg * H_ + xc;
                    float z0 = (float)dhi[2*i+0] * S_HI
                             + (float)(dmA[2*i+0] + dmB[2*i+0]) * S_MID + xv[i].x;
                    float z1 = (float)dhi[2*i+1] * S_HI
                             + (float)(dmA[2*i+1] + dmB[2*i+1]) * S_MID + xv[i].y;
                    float s0 = 1.0f / (1.0f + __expf(-z0));
                    float s1 = 1.0f / (1.0f + __expf(-z1));
                    if (cb < 16) {
                        float v0 = hv[i].x * s0, v1 = hv[i].y * s1;
                        int q0 = __float2int_rn(v0 * 16384.0f);
                        int q1 = __float2int_rn(v1 * 16384.0f);
                        int p0 = (q0 + 128) >> 8, p1 = (q1 + 128) >> 8;
                        int r0q = q0 - (p0 << 8), r1q = q1 - (p1 << 8);
                        unsigned short hi2 = (unsigned short)((p0 & 0xFF) | ((p1 & 0xFF) << 8));
                        unsigned short lo2 = (unsigned short)((r0q & 0xFF) | ((r1q & 0xFF) << 8));
                        size_t sa = (size_t)rowg * 1024 +
                                    ((((xc >> 4) ^ (rowg & 7)) << 4) | (xc & 15));
                        __stcg(reinterpret_cast<unsigned short*>(g_hR1 + sa), hi2);
                        __stcg(reinterpret_cast<unsigned short*>(g_hR0 + sa), lo2);
                    } else {
                        __stcg(reinterpret_cast<float2*>(g_U + off), make_float2(s0, s1));
                    }
                }
            }
            grp_arrive(&g_barA[rg]);
            grp_wait(&g_barA[rg], tgt);

            // ======= phase B: candidate + update (16 rows x 32 cols) =======
            {
                const int gc = cc0 + (wid & 3) * 8 + (lane & 3) * 2;
                float2 xv[2], uv[2], hv[2];
                if (wid < 4) {
#pragma unroll
                    for (int i = 0; i < 2; i++) {
                        const int rowg = r0 + (lane >> 2) + i * 8;
                        const size_t off = (size_t)rowg * H_ + gc;
                        xv[i] = __ldcg(reinterpret_cast<const float2*>(g_x[2] + xbase + off));
                        uv[i] = __ldcg(reinterpret_cast<const float2*>(g_U + off));
                        hv[i] = __ldcg(reinterpret_cast<const float2*>(g_h + off));
                    }
                }
                if (tid == 0) {
                    asm volatile("mbarrier.arrive.expect_tx.shared.b64 _, [%0], %1;"
                                 :: "r"(mb), "r"(32768u) : "memory");
                    bulk_g2s(sbase + QH1, g_hR1 + (size_t)r0 * 1024, 16384u, mb);
                    bulk_g2s(sbase + QH0, g_hR0 + (size_t)r0 * 1024, 16384u, mb);
                }
                MBAR_WAIT(mb, par);
                par ^= 1;

                int dhi[4] = {0,0,0,0}, dmA[4] = {0,0,0,0}, dmB[4] = {0,0,0,0};
                {
                    const uint32_t baseA1 = sbase + QH1 + rA * 1024;
                    const uint32_t baseA0 = sbase + QH0 + rA * 1024;
                    const uint32_t baseB1 = sbase + QW1B + rBb * 1024;
                    const uint32_t baseB0 = sbase + QW0B + rBb * 1024;
                    const int ks0 = (wid >> 2) * 16;
#pragma unroll 8
                    for (int ks = ks0; ks < ks0 + 16; ks++) {
                        const uint32_t uA = (((uint32_t)ks * 2 + selA) ^ swA) << 4;
                        const uint32_t uB = (((uint32_t)ks * 2 + selB) ^ swBb) << 4;
                        uint32_t a1[4], a0[4], b1[2], b0[2];
                        ldsm4(a1, baseA1 + uA);
                        ldsm4(a0, baseA0 + uA);
                        ldsm2(b1, baseB1 + uB);
                        ldsm2(b0, baseB0 + uB);
                        imma32(dhi, a1, b1[0], b1[1]);
                        imma32(dmA, a1, b0[0], b0[1]);
                        imma32(dmB, a0, b1[0], b1[1]);
                    }
                }
                __syncthreads();   // MMA done; QH region reusable for reduction
                if (wid >= 4) {
                    int* rb = reinterpret_cast<int*>(smc + QRED)
                              + (((wid - 4) * 32 + lane) * 12);
#pragma unroll
                    for (int j = 0; j < 4; j++) { rb[j] = dhi[j]; rb[4 + j] = dmA[j]; rb[8 + j] = dmB[j]; }
                }
                __syncthreads();
                if (wid < 4) {
                    const int* rb = reinterpret_cast<const int*>(smc + QRED)
                                    + ((wid * 32 + lane) * 12);
#pragma unroll
                    for (int j = 0; j < 4; j++) { dhi[j] += rb[j]; dmA[j] += rb[4 + j]; dmB[j] += rb[8 + j]; }

#pragma unroll
                    for (int i = 0; i < 2; i++) {
                        const int rowg = r0 + (lane >> 2) + i * 8;
                        const size_t off = (size_t)rowg * H_ + gc;
                        float z0 = (float)dhi[2*i+0] * S_HI
                                 + (float)(dmA[2*i+0] + dmB[2*i+0]) * S_MID + xv[i].x;
                        float z1 = (float)dhi[2*i+1] * S_HI
                                 + (float)(dmA[2*i+1] + dmB[2*i+1]) * S_MID + xv[i].y;
                        float hc0 = tanhf(z0), hc1 = tanhf(z1);
                        float hn0 = uv[i].x * hv[i].x + (1.0f - uv[i].x) * hc0;
                        float hn1 = uv[i].y * hv[i].y + (1.0f - uv[i].y) * hc1;
                        __stcg(reinterpret_cast<float2*>(g_h + off), make_float2(hn0, hn1));
                        __stcg(reinterpret_cast<float2*>(states + xbase + off),
                               make_float2(hn0, hn1));
                        __nv_bfloat16 b0 = __float2bfloat16(hn0);
                        __nv_bfloat16 b1 = __float2bfloat16(hn1);
                        unsigned short u0 = *reinterpret_cast<unsigned short*>(&b0);
                        unsigned short u1 = *reinterpret_cast<unsigned short*>(&b1);
                        __nv_bfloat16 l0 = __float2bfloat16(hn0 - __bfloat162float(b0));
                        __nv_bfloat16 l1 = __float2bfloat16(hn1 - __bfloat162float(b1));
                        unsigned short v0 = *reinterpret_cast<unsigned short*>(&l0);
                        unsigned short v1 = *reinterpret_cast<unsigned short*>(&l1);
                        __stcg(reinterpret_cast<unsigned int*>(g_Sh + xbase + off),
                               ((unsigned)u1 << 16) | u0);
                        __stcg(reinterpret_cast<unsigned int*>(g_Sl + xbase + off),
                               ((unsigned)v1 << 16) | v0);
                        int q0 = __float2int_rn(hn0 * 16384.0f);
                        int q1 = __float2int_rn(hn1 * 16384.0f);
                        int p0 = (q0 + 128) >> 8, p1 = (q1 + 128) >> 8;
                        int r0q = q0 - (p0 << 8), r1q = q1 - (p1 << 8);
                        unsigned short hi2 = (unsigned short)((p0 & 0xFF) | ((p1 & 0xFF) << 8));
                        unsigned short lo2 = (unsigned short)((r0q & 0xFF) | ((r1q & 0xFF) << 8));
                        size_t sa = (size_t)rowg * 1024 +
                                    ((((gc >> 4) ^ (rowg & 7)) << 4) | (gc & 15));
                        __stcg(reinterpret_cast<unsigned short*>(g_h1 + sa), hi2);
                        __stcg(reinterpret_cast<unsigned short*>(g_h0 + sa), lo2);
                    }
                }
            }
            grp_arrive(&g_barB[rg]);
            grp_wait(&g_barB[rg], tgt);
        }
        // fall through: help with the output projection
    }

    // =================== output-projection work queue ===================
    volatile int* tile_sh = reinterpret_cast<volatile int*>(smc + QMB + 16);
    for (;;) {
        if (tid == 0)
            *tile_sh = (int)atomicAdd(&g_tile_ctr, 1u);
        __syncthreads();
        const int tile = *tile_sh;
        __syncthreads();
        if (tile >= NOUT_TILES) break;
        const int mt = tile >> 3;
        const int nt = tile & 7;
        if (tid == 0) {
            const unsigned target = (unsigned)(2 * mt + 2) * 32;
#pragma unroll
            for (int g = 0; g < 4; g++) {
                unsigned v;
                do {
                    asm volatile("ld.acquire.gpu.global.u32 %0, [%1];"
                                 : "=r"(v) : "l"(&g_barB[g]) : "memory");
                } while (v < target);
            }
        }
        __syncthreads();
        hmma_tile_body(g_Sh, g_Sl, g_Bh[3], g_Bl[3], b_q, outputs,
                       mt * 128, nt * 128, nt * 128, smc);
        __syncthreads();
    }
}

// ================== launcher ===================================================
extern "C" void kernel_launch(void* const* d_in, const int* in_sizes, int n_in,
                              void* d_out, int out_size)
{
    const float* X    = (const float*)d_in[0];
    const float* W_xr = (const float*)d_in[1];
    const float* W_xu = (const float*)d_in[2];
    const float* W_xh = (const float*)d_in[3];
    const float* W_hr = (const float*)d_in[4];
    const float* W_hu = (const float*)d_in[5];
    const float* W_hh = (const float*)d_in[6];
    const float* b_r  = (const float*)d_in[7];
    const float* b_u  = (const float*)d_in[8];
    const float* b_h  = (const float*)d_in[9];
    const float* W_hq = (const float*)d_in[10];
    const float* b_q  = (const float*)d_in[11];

    float* out     = (float*)d_out;
    float* outputs = out;                        // [T,B,O]
    float* states  = out + (size_t)TB_ * O_;     // [T,B,H]

    void *p_x, *p_ah, *p_al, *p_bh, *p_bl;
    cudaGetSymbolAddress(&p_x, g_x);
    cudaGetSymbolAddress(&p_ah, g_Ah);
    cudaGetSymbolAddress(&p_al, g_Al);
    cudaGetSymbolAddress(&p_bh, g_Bh);
    cudaGetSymbolAddress(&p_bl, g_Bl);

    float* xbuf = (float*)p_x;
    __nv_bfloat16* Ah = (__nv_bfloat16*)p_ah;
    __nv_bfloat16* Al = (__nv_bfloat16*)p_al;
    __nv_bfloat16* Bh = (__nv_bfloat16*)p_bh;
    __nv_bfloat16* Bl = (__nv_bfloat16*)p_bl;

    static int smem_set = 0;
    if (!smem_set) {
        cudaFuncSetAttribute(hmma_gemm3_kernel,
                             cudaFuncAttributeMaxDynamicSharedMemorySize, GEMM_SMEM);
        cudaFuncSetAttribute(gru_mega_kernel,
                             cudaFuncAttributeMaxDynamicSharedMemorySize, RSMEM);
        smem_set = 1;
    }

    // 0: fused prep
    prep_all<<<61696, 256>>>(X, W_xr, W_xu, W_xh, W_hq, W_hr, W_hu, W_hh);
    // 1: fused input projections (full device)
    {
        ProjOut po;
        po.b[0] = b_r; po.b[1] = b_u; po.b[2] = b_h;
        po.c[0] = xbuf; po.c[1] = xbuf + (size_t)TB_ * H_; po.c[2] = xbuf + 2 * (size_t)TB_ * H_;
        dim3 gg(24, TB_ / 128);
        hmma_gemm3_kernel<<<gg, 256, GEMM_SMEM>>>(Ah, Al, Bh, Bl, po);
    }
    // 2: mega kernel — 2-D recurrence (128 blocks) + work-stealing output proj
    gru_mega_kernel<<<NBLK + 24, 256, RSMEM>>>(states, outputs, b_q);
}